// round 15
// baseline (speedup 1.0000x reference)
#include <cuda_runtime.h>
#include <cuda_fp16.h>
#include <cstdint>

#define BB 8
#define NN 4096
#define DD 128
#define SCALE 0.08838834764831845f
#define LOG2E 1.4426950408889634f
#define QS (SCALE * LOG2E)

#define BM 64
#define BN 64
#define NT (NN / BN)

typedef unsigned long long u64;

// scratch (no cudaMalloc allowed)
__device__ __half g_kh[(size_t)BB * NN * DD];
__device__ __half g_vh[(size_t)BB * NN * DD];
__device__ __half g_qh[(size_t)BB * NN * DD];

// ---- attention smem (bytes), BM=64. K/Q/V pitch 136 halves, P pitch 72 ----
#define TBUF  17408
#define PBUF  9216
#define SM_K  0                  /* 64 rows              17408 */
#define SM_Q  17408              /* 2 bufs               34816 */
#define SM_V  52224              /* 2 bufs               34816 */
#define SM_P  87040              /* 2 bufs                18432 */
#define SM_LS 105472
#define SM_TOT 105984

// ---- PTX helpers ----
__device__ __forceinline__ uint32_t smem_u32(const void* p) {
    uint32_t a;
    asm("{ .reg .u64 t; cvta.to.shared.u64 t,%1; cvt.u32.u64 %0,t; }" : "=r"(a) : "l"(p));
    return a;
}
__device__ __forceinline__ void ldsmx4(uint32_t* r, uint32_t a) {
    asm volatile("ldmatrix.sync.aligned.m8n8.x4.shared.b16 {%0,%1,%2,%3},[%4];"
                 : "=r"(r[0]), "=r"(r[1]), "=r"(r[2]), "=r"(r[3]) : "r"(a));
}
__device__ __forceinline__ void ldsmx4t(uint32_t* r, uint32_t a) {
    asm volatile("ldmatrix.sync.aligned.m8n8.x4.trans.shared.b16 {%0,%1,%2,%3},[%4];"
                 : "=r"(r[0]), "=r"(r[1]), "=r"(r[2]), "=r"(r[3]) : "r"(a));
}
__device__ __forceinline__ void mma16816(float* c, const uint32_t* a, uint32_t b0, uint32_t b1) {
    asm volatile(
        "mma.sync.aligned.m16n8k16.row.col.f32.f16.f16.f32 "
        "{%0,%1,%2,%3},{%4,%5,%6,%7},{%8,%9},{%0,%1,%2,%3};"
        : "+f"(c[0]), "+f"(c[1]), "+f"(c[2]), "+f"(c[3])
        : "r"(a[0]), "r"(a[1]), "r"(a[2]), "r"(a[3]), "r"(b0), "r"(b1));
}
__device__ __forceinline__ float ex2(float x) {
    float y; asm("ex2.approx.f32 %0,%1;" : "=f"(y) : "f"(x)); return y;
}
__device__ __forceinline__ uint32_t packh2(float lo, float hi) {  // lo -> bits[0:16)
    uint32_t r; asm("cvt.rn.f16x2.f32 %0,%1,%2;" : "=r"(r) : "f"(hi), "f"(lo)); return r;
}
#define CPA16(dst, src) \
    asm volatile("cp.async.cg.shared.global [%0],[%1],16;" :: "r"(dst), "l"(src))
#define CPA_COMMIT() asm volatile("cp.async.commit_group;" ::: "memory")
#define CPA_WAIT0()  asm volatile("cp.async.wait_group 0;" ::: "memory")
#define BAR_SYNC(id, cnt) \
    asm volatile("bar.sync %0, %1;" :: "r"(id), "r"(cnt) : "memory")
#define BAR_ARRIVE(id, cnt) \
    asm volatile("bar.arrive %0, %1;" :: "r"(id), "r"(cnt) : "memory")

// ============================================================================
// Warp-specialized attention + fused output projection. BM=64, 128 thr,
// 2 CTAs/SM (cross-CTA overlap) x producer/consumer split (intra-CTA overlap).
// Warps 0-1 (producers): S(jt)=K@Q^T, P=exp2(S)->smem (2 bufs), l.
// Warps 2-3 (consumers): O += P(jt)@V(jt), full d=128 per warp.
// Barriers: 1/2 = P ready (even/odd jt), 3/4 = P buf free, 5/6 internal.
// ============================================================================
__global__ void __launch_bounds__(128, 2)
attn_mma(const __half* __restrict__ khg, const __half* __restrict__ vhg,
         const __half* __restrict__ qhg, const float* __restrict__ Wp,
         const float* __restrict__ bp, float* __restrict__ out) {
    extern __shared__ char smem[];
    const uint32_t sb = smem_u32(smem);
    const int tid = threadIdx.x, lane = tid & 31, wid = tid >> 5;
    const int q = lane & 3, lr = lane >> 2;
    const int b = blockIdx.y, row0 = blockIdx.x * BM;

    const __half* kh_b = khg + ((size_t)b * NN + row0) * DD;
    const __half* vh_b = vhg + (size_t)b * NN * DD;
    const __half* qh_b = qhg + (size_t)b * NN * DD;

    const int rA = (lane & 7) + (lane & 8), cA = (lane & 16) >> 1;   // A/P/V pattern
    const int rB = (lane & 7) + ((lane & 16) >> 1), cB = lane & 8;   // B (Q) pattern

    // ---- prologue: stage K (all threads), prefetch Q(0)/V(0) by group ----
    #pragma unroll
    for (int t = 0; t < 8; ++t) {
        int c = tid + (t << 7);
        int r = c >> 4, c16 = c & 15;
        *(uint4*)(smem + SM_K + (uint32_t)(r * 272 + c16 * 16)) =
            *(const uint4*)((const char*)(kh_b + (size_t)r * DD) + c16 * 16);
    }
    if (wid < 2) {
        const int gt = tid;            // 0..63
        #pragma unroll
        for (int t = 0; t < 16; ++t) {
            int c = gt + (t << 6);
            int m = c >> 4, c16 = c & 15;
            CPA16(sb + SM_Q + (uint32_t)(m * 272 + c16 * 16),
                  (const char*)(qh_b + (size_t)m * DD) + c16 * 16);
        }
    } else {
        const int gt = tid - 64;       // 0..63
        #pragma unroll
        for (int t = 0; t < 16; ++t) {
            int c = gt + (t << 6);
            int m = c >> 4, c16 = c & 15;
            CPA16(sb + SM_V + (uint32_t)(m * 272 + c16 * 16),
                  (const char*)(vh_b + (size_t)m * DD) + c16 * 16);
        }
    }
    CPA_COMMIT();
    __syncthreads();   // K visible to all

    float lloc[4] = {0.f, 0.f, 0.f, 0.f};   // producers only
    float sO[2][16][4];                      // consumers only (128 regs)
    #pragma unroll
    for (int i = 0; i < 2; ++i)
        #pragma unroll
        for (int j = 0; j < 16; ++j) {
            sO[i][j][0] = 0.f; sO[i][j][1] = 0.f; sO[i][j][2] = 0.f; sO[i][j][3] = 0.f;
        }

    if (wid < 2) {
        // ===================== PRODUCER (warps 0-1) =====================
        const int gt = tid;
        uint32_t aK[2], bQ[2][4];
        #pragma unroll
        for (int mt = 0; mt < 2; ++mt)
            aK[mt] = sb + SM_K + 2u * ((32 * wid + 16 * mt + rA) * 136 + cA);
        #pragma unroll
        for (int bf = 0; bf < 2; ++bf)
            #pragma unroll
            for (int bt = 0; bt < 4; ++bt)
                bQ[bf][bt] = sb + SM_Q + bf * TBUF + 2u * ((16 * bt + rB) * 136 + cB);

        for (int jt = 0; jt < NT; ++jt) {
            CPA_WAIT0();
            BAR_SYNC(5, 64);   // Q(jt) visible group-wide; all past S(jt-1)

            if (jt + 1 < NT) {  // prefetch Q(jt+1)
                const size_t m1 = (size_t)(jt + 1) * BN;
                const uint32_t dst = sb + SM_Q + ((jt + 1) & 1) * TBUF;
                #pragma unroll
                for (int t = 0; t < 16; ++t) {
                    int c = gt + (t << 6);
                    int m = c >> 4, c16 = c & 15;
                    CPA16(dst + (uint32_t)(m * 272 + c16 * 16),
                          (const char*)(qh_b + (m1 + m) * DD) + c16 * 16);
                }
                CPA_COMMIT();
            }

            // S(jt): 32 rows x 64 cols per warp, 8 k-steps
            float sC[2][8][4];
            #pragma unroll
            for (int i = 0; i < 2; ++i)
                #pragma unroll
                for (int j = 0; j < 8; ++j) {
                    sC[i][j][0] = 0.f; sC[i][j][1] = 0.f;
                    sC[i][j][2] = 0.f; sC[i][j][3] = 0.f;
                }
            const int qb = jt & 1;
            #pragma unroll
            for (int ks = 0; ks < 8; ++ks) {
                uint32_t kf[2][4], qf[4][4];
                #pragma unroll
                for (int mt = 0; mt < 2; ++mt) ldsmx4(kf[mt], aK[mt] + ks * 32);
                #pragma unroll
                for (int bt = 0; bt < 4; ++bt) ldsmx4(qf[bt], bQ[qb][bt] + ks * 32);
                #pragma unroll
                for (int mt = 0; mt < 2; ++mt)
                    #pragma unroll
                    for (int nt = 0; nt < 8; ++nt)
                        mma16816(sC[mt][nt], kf[mt],
                                 qf[nt >> 1][2 * (nt & 1)], qf[nt >> 1][2 * (nt & 1) + 1]);
            }

            if (jt >= 2) BAR_SYNC(3 + (jt & 1), 128);   // P buf free

            // P(jt) = exp2(S) -> smem (buf jt&1), accumulate l
            const uint32_t poff = SM_P + (jt & 1) * PBUF;
            #pragma unroll
            for (int mt = 0; mt < 2; ++mt) {
                int rbase = 32 * wid + 16 * mt + lr;
                #pragma unroll
                for (int nt = 0; nt < 8; ++nt) {
                    int col = 8 * nt + 2 * q;
                    float p0 = ex2(sC[mt][nt][0]), p1 = ex2(sC[mt][nt][1]);
                    float p2 = ex2(sC[mt][nt][2]), p3 = ex2(sC[mt][nt][3]);
                    lloc[2 * mt] += p0 + p1;
                    lloc[2 * mt + 1] += p2 + p3;
                    *(uint32_t*)(smem + poff + 2u * (rbase * 72 + col)) =
                        packh2(p0, p1);
                    *(uint32_t*)(smem + poff + 2u * ((rbase + 8) * 72 + col)) =
                        packh2(p2, p3);
                }
            }
            BAR_ARRIVE(1 + (jt & 1), 128);   // P(jt) ready
        }
    } else {
        // ===================== CONSUMER (warps 2-3) =====================
        const int gt = tid - 64;
        const int w2 = wid - 2;
        uint32_t aP[2][2], bV[2][8];
        #pragma unroll
        for (int bf = 0; bf < 2; ++bf) {
            #pragma unroll
            for (int mt = 0; mt < 2; ++mt)
                aP[bf][mt] = sb + SM_P + bf * PBUF +
                             2u * ((32 * w2 + 16 * mt + rA) * 72 + cA);
            #pragma unroll
            for (int bt = 0; bt < 8; ++bt)
                bV[bf][bt] = sb + SM_V + bf * TBUF +
                             2u * (rA * 136 + 16 * bt + cA);
        }

        for (int jt = 0; jt < NT; ++jt) {
            CPA_WAIT0();
            BAR_SYNC(6, 64);   // V(jt) visible group-wide; all past PV(jt-1)

            if (jt + 1 < NT) {  // prefetch V(jt+1)
                const size_t m1 = (size_t)(jt + 1) * BN;
                const uint32_t dst = sb + SM_V + ((jt + 1) & 1) * TBUF;
                #pragma unroll
                for (int t = 0; t < 16; ++t) {
                    int c = gt + (t << 6);
                    int m = c >> 4, c16 = c & 15;
                    CPA16(dst + (uint32_t)(m * 272 + c16 * 16),
                          (const char*)(vh_b + (m1 + m) * DD) + c16 * 16);
                }
                CPA_COMMIT();
            }

            BAR_SYNC(1 + (jt & 1), 128);   // P(jt) ready

            // PV(jt): 32 rows x 128 d per warp, 4 k-steps
            const int vb = jt & 1;
            #pragma unroll
            for (int ks = 0; ks < 4; ++ks) {
                uint32_t ph[2][4], vf[8][4];
                #pragma unroll
                for (int mt = 0; mt < 2; ++mt) ldsmx4(ph[mt], aP[vb][mt] + ks * 32);
                #pragma unroll
                for (int bt = 0; bt < 8; ++bt) ldsmx4t(vf[bt], bV[vb][bt] + ks * 4352);
                #pragma unroll
                for (int mt = 0; mt < 2; ++mt)
                    #pragma unroll
                    for (int nt = 0; nt < 16; ++nt)
                        mma16816(sO[mt][nt], ph[mt],
                                 vf[nt >> 1][2 * (nt & 1)], vf[nt >> 1][2 * (nt & 1) + 1]);
            }

            if (jt <= NT - 3) BAR_ARRIVE(3 + (jt & 1), 128);   // P buf free
        }
    }
    __syncthreads();

    // ---- l: producers quad-reduce + write lsum (rows 0..63) ----
    float* lsum = (float*)(smem + SM_LS);
    if (wid < 2) {
        #pragma unroll
        for (int i = 0; i < 4; ++i) {
            lloc[i] += __shfl_xor_sync(0xffffffffu, lloc[i], 1);
            lloc[i] += __shfl_xor_sync(0xffffffffu, lloc[i], 2);
        }
        if (q == 0) {
            #pragma unroll
            for (int i = 0; i < 4; ++i) {
                int row = 32 * wid + 16 * (i >> 1) + 8 * (i & 1) + lr;
                lsum[row] = lloc[i];
            }
        }
    }
    __syncthreads();

    // ---- epilogue staging: consumers Onorm->SM_K; producers Wp->SM_Q..SM_V ----
    if (wid >= 2) {
        const int w2 = wid - 2;
        #pragma unroll
        for (int mt = 0; mt < 2; ++mt) {
            int ra = 32 * w2 + 16 * mt + lr;
            float inva = 1.0f / lsum[ra];
            float invb = 1.0f / lsum[ra + 8];
            #pragma unroll
            for (int nt = 0; nt < 16; ++nt) {
                int col = 8 * nt + 2 * q;
                *(uint32_t*)(smem + SM_K + 2u * (ra * 136 + col)) =
                    packh2(sO[mt][nt][0] * inva, sO[mt][nt][1] * inva);
                *(uint32_t*)(smem + SM_K + 2u * ((ra + 8) * 136 + col)) =
                    packh2(sO[mt][nt][2] * invb, sO[mt][nt][3] * invb);
            }
        }
    } else {
        const int gt = tid;   // 0..63: Wp 128 rows x 32 8B-chunks
        #pragma unroll
        for (int t = 0; t < 64; ++t) {
            int c = gt + (t << 6);
            int k = c >> 5, c4 = c & 31;
            float4 v = *(const float4*)(Wp + (size_t)k * 128 + (c4 << 2));
            uint2 h; h.x = packh2(v.x, v.y); h.y = packh2(v.z, v.w);
            *(uint2*)(smem + SM_Q + (uint32_t)(k * 272 + (c4 << 3))) = h;
        }
    }
    __syncthreads();

    // ---- fused projection: out = Onorm @ Wp + bp (all 4 warps, 64x128) ----
    {
        uint32_t aB[4], bB[2];
        #pragma unroll
        for (int mt = 0; mt < 4; ++mt)
            aB[mt] = sb + SM_K + 2u * ((16 * mt + rA) * 136 + cA);
        #pragma unroll
        for (int bt = 0; bt < 2; ++bt)
            bB[bt] = sb + SM_Q + 2u * (rA * 136 + 32 * wid + 16 * bt + cA);

        float acc[4][4][4];
        #pragma unroll
        for (int i = 0; i < 4; ++i)
            #pragma unroll
            for (int j = 0; j < 4; ++j) {
                acc[i][j][0] = 0.f; acc[i][j][1] = 0.f;
                acc[i][j][2] = 0.f; acc[i][j][3] = 0.f;
            }
        #pragma unroll
        for (int ks = 0; ks < 8; ++ks) {
            uint32_t a[4][4], bf[2][4];
            #pragma unroll
            for (int mt = 0; mt < 4; ++mt) ldsmx4(a[mt], aB[mt] + ks * 32);
            #pragma unroll
            for (int bt = 0; bt < 2; ++bt) ldsmx4t(bf[bt], bB[bt] + ks * 4352);
            #pragma unroll
            for (int mt = 0; mt < 4; ++mt)
                #pragma unroll
                for (int nt = 0; nt < 4; ++nt)
                    mma16816(acc[mt][nt], a[mt],
                             bf[nt >> 1][2 * (nt & 1)], bf[nt >> 1][2 * (nt & 1) + 1]);
        }

        float* ob = out + ((size_t)b * NN + row0) * DD;
        #pragma unroll
        for (int mt = 0; mt < 4; ++mt) {
            int ra = 16 * mt + lr;
            #pragma unroll
            for (int nt = 0; nt < 4; ++nt) {
                int col = 32 * wid + 8 * nt + 2 * q;
                float b0 = bp[col], b1 = bp[col + 1];
                *(float2*)(ob + (size_t)ra * DD + col) =
                    make_float2(acc[mt][nt][0] + b0, acc[mt][nt][1] + b1);
                *(float2*)(ob + (size_t)(ra + 8) * DD + col) =
                    make_float2(acc[mt][nt][2] + b0, acc[mt][nt][3] + b1);
            }
        }
    }
}

// ============================================================================
// fp16 tensor-core kv projection (128x128 CTA tile) + fused Q conversion
// ============================================================================
__device__ __forceinline__ uint32_t pack_us2(__half a, __half b) {
    return (uint32_t)__half_as_ushort(a) | ((uint32_t)__half_as_ushort(b) << 16);
}

__global__ void __launch_bounds__(256, 2)
gemm16_kv(const float* __restrict__ A, const float* __restrict__ W,
          const float* __restrict__ bias, const float* __restrict__ qg,
          __half* __restrict__ kh, __half* __restrict__ vh,
          __half* __restrict__ qh) {
    if (blockIdx.x == 2) {   // fused qconv: 128 rows of Q per y-block
        const size_t base = (size_t)blockIdx.y * (128 * 128 / 4);
        const float4* src = (const float4*)qg + base;
        __half2* dst = (__half2*)qh + base * 2;
        #pragma unroll
        for (int t = 0; t < 16; ++t) {
            int f = threadIdx.x + (t << 8);
            float4 v = src[f];
            dst[2 * f]     = __floats2half2_rn(v.x * QS, v.y * QS);
            dst[2 * f + 1] = __floats2half2_rn(v.z * QS, v.w * QS);
        }
        return;
    }

    extern __shared__ char smg[];
    const uint32_t sb = smem_u32(smg);
    const int tid = threadIdx.x, lane = tid & 31, wid = tid >> 5;
    const int q = lane & 3, lr = lane >> 2;
    const int rw = wid >> 2, cw = wid & 3;
    const int row0 = blockIdx.y * 128, col0 = blockIdx.x * 128;

    #pragma unroll
    for (int it = 0; it < 16; ++it) {
        int f = tid + (it << 8);
        int r = f >> 5, c4 = f & 31;
        float4 v = *(const float4*)(A + (size_t)(row0 + r) * 128 + (c4 << 2));
        uint2 h; h.x = packh2(v.x, v.y); h.y = packh2(v.z, v.w);
        *(uint2*)(smg + (uint32_t)(r * 272 + (c4 << 3))) = h;
    }
    #pragma unroll
    for (int it = 0; it < 16; ++it) {
        int f = tid + (it << 8);
        int k = f >> 5, c4 = f & 31;
        float4 v = *(const float4*)(W + (size_t)k * 256 + col0 + (c4 << 2));
        uint2 h; h.x = packh2(v.x, v.y); h.y = packh2(v.z, v.w);
        *(uint2*)(smg + 34816 + (uint32_t)(k * 272 + (c4 << 3))) = h;
    }
    __syncthreads();

    const int rA = (lane & 7) + (lane & 8), cA = (lane & 16) >> 1;
    uint32_t aBase[4], bBase[2];
    #pragma unroll
    for (int mt = 0; mt < 4; ++mt)
        aBase[mt] = sb + 2u * ((64 * rw + 16 * mt + rA) * 136 + cA);
    #pragma unroll
    for (int bt = 0; bt < 2; ++bt)
        bBase[bt] = sb + 34816 + 2u * (rA * 136 + 32 * cw + 16 * bt + cA);

    float acc[4][4][4];
    #pragma unroll
    for (int i = 0; i < 4; ++i)
        #pragma unroll
        for (int j = 0; j < 4; ++j) {
            acc[i][j][0] = 0.f; acc[i][j][1] = 0.f; acc[i][j][2] = 0.f; acc[i][j][3] = 0.f;
        }
    #pragma unroll
    for (int ks = 0; ks < 8; ++ks) {
        uint32_t a[4][4], bf[2][4];
        #pragma unroll
        for (int mt = 0; mt < 4; ++mt) ldsmx4(a[mt], aBase[mt] + ks * 32);
        #pragma unroll
        for (int bt = 0; bt < 2; ++bt) ldsmx4t(bf[bt], bBase[bt] + ks * 4352);
        #pragma unroll
        for (int mt = 0; mt < 4; ++mt)
            #pragma unroll
            for (int nt = 0; nt < 4; ++nt)
                mma16816(acc[mt][nt], a[mt],
                         bf[nt >> 1][2 * (nt & 1)], bf[nt >> 1][2 * (nt & 1) + 1]);
    }

    __half* dh = (col0 == 0) ? kh : vh;
    #pragma unroll
    for (int mt = 0; mt < 4; ++mt) {
        int r = row0 + 64 * rw + 16 * mt + lr;
        #pragma unroll
        for (int nt = 0; nt < 4; ++nt) {
            int col = 32 * cw + 8 * nt + 2 * q;
            float b0 = bias[col0 + col], b1 = bias[col0 + col + 1];
            *(uint32_t*)(dh + (size_t)r * 128 + col) = pack_us2(
                __float2half_rn(acc[mt][nt][0] + b0), __float2half_rn(acc[mt][nt][1] + b1));
            *(uint32_t*)(dh + (size_t)(r + 8) * 128 + col) = pack_us2(
                __float2half_rn(acc[mt][nt][2] + b0), __float2half_rn(acc[mt][nt][3] + b1));
        }
    }
}

// ============================================================================
extern "C" void kernel_launch(void* const* d_in, const int* in_sizes, int n_in,
                              void* d_out, int out_size) {
    const float* x   = (const float*)d_in[0];
    const float* qg  = (const float*)d_in[1];
    const float* Wkv = (const float*)d_in[2];
    const float* bkv = (const float*)d_in[3];
    const float* Wp  = (const float*)d_in[4];
    const float* bp  = (const float*)d_in[5];
    float* out = (float*)d_out;

    __half *khp, *vhp, *qhp;
    cudaGetSymbolAddress((void**)&khp, g_kh);
    cudaGetSymbolAddress((void**)&vhp, g_vh);
    cudaGetSymbolAddress((void**)&qhp, g_qh);

    const int M = BB * NN;
    const int gsm = 2 * 128 * 272;  // 69632 B

    cudaFuncSetAttribute(gemm16_kv,
                         cudaFuncAttributeMaxDynamicSharedMemorySize, gsm);
    cudaFuncSetAttribute(attn_mma,
                         cudaFuncAttributeMaxDynamicSharedMemorySize, SM_TOT);

    gemm16_kv<<<dim3(3, M / 128), 256, gsm>>>(x, Wkv, bkv, qg, khp, vhp, qhp);
    attn_mma<<<dim3(NN / BM, BB), 128, SM_TOT>>>(khp, vhp, qhp, Wp, bp, out);
}

// round 16
// speedup vs baseline: 1.1130x; 1.1130x over previous
#include <cuda_runtime.h>
#include <cuda_fp16.h>
#include <cstdint>

#define BB 8
#define NN 4096
#define DD 128
#define SCALE 0.08838834764831845f
#define LOG2E 1.4426950408889634f
#define QS (SCALE * LOG2E)

#define BM 128
#define BN 64
#define NT (NN / BN)

typedef unsigned long long u64;

// scratch (no cudaMalloc allowed)
__device__ __half g_kh[(size_t)BB * NN * DD];
__device__ __half g_vh[(size_t)BB * NN * DD];
__device__ __half g_qh[(size_t)BB * NN * DD];

// ---- attention smem (bytes). K/Q/V pitch 136 halves (272B), P pitch 72 ----
// K resident 34816 | Q 1 buf 17408 | V 2 bufs 34816 | P 18432 | lsum 1KB
// epilogue reuse: O fp16 -> SM_K region, Wp fp16 -> SM_Q region
#define SM_K  0
#define SM_Q  34816
#define SM_V  52224
#define TBUF  17408
#define SM_P  87040
#define SM_LS 105472
#define SM_TOT 106496

// ---- PTX helpers ----
__device__ __forceinline__ uint32_t smem_u32(const void* p) {
    uint32_t a;
    asm("{ .reg .u64 t; cvta.to.shared.u64 t,%1; cvt.u32.u64 %0,t; }" : "=r"(a) : "l"(p));
    return a;
}
__device__ __forceinline__ void ldsmx4(uint32_t* r, uint32_t a) {
    asm volatile("ldmatrix.sync.aligned.m8n8.x4.shared.b16 {%0,%1,%2,%3},[%4];"
                 : "=r"(r[0]), "=r"(r[1]), "=r"(r[2]), "=r"(r[3]) : "r"(a));
}
__device__ __forceinline__ void ldsmx4t(uint32_t* r, uint32_t a) {
    asm volatile("ldmatrix.sync.aligned.m8n8.x4.trans.shared.b16 {%0,%1,%2,%3},[%4];"
                 : "=r"(r[0]), "=r"(r[1]), "=r"(r[2]), "=r"(r[3]) : "r"(a));
}
__device__ __forceinline__ void mma16816(float* c, const uint32_t* a, uint32_t b0, uint32_t b1) {
    asm volatile(
        "mma.sync.aligned.m16n8k16.row.col.f32.f16.f16.f32 "
        "{%0,%1,%2,%3},{%4,%5,%6,%7},{%8,%9},{%0,%1,%2,%3};"
        : "+f"(c[0]), "+f"(c[1]), "+f"(c[2]), "+f"(c[3])
        : "r"(a[0]), "r"(a[1]), "r"(a[2]), "r"(a[3]), "r"(b0), "r"(b1));
}
__device__ __forceinline__ uint32_t packh2(float lo, float hi) {  // lo -> bits[0:16)
    uint32_t r; asm("cvt.rn.f16x2.f32 %0,%1,%2;" : "=r"(r) : "f"(hi), "f"(lo)); return r;
}
__device__ __forceinline__ uint32_t ex2h2(uint32_t x) {  // dual fp16 exp2
    uint32_t y; asm("ex2.approx.f16x2 %0,%1;" : "=r"(y) : "r"(x)); return y;
}
__device__ __forceinline__ uint32_t hadd2(uint32_t a, uint32_t b) {
    uint32_t d; asm("add.rn.f16x2 %0,%1,%2;" : "=r"(d) : "r"(a), "r"(b)); return d;
}
__device__ __forceinline__ float h2lo(uint32_t w) {
    return __half2float(__ushort_as_half((unsigned short)(w & 0xffff)));
}
__device__ __forceinline__ float h2hi(uint32_t w) {
    return __half2float(__ushort_as_half((unsigned short)(w >> 16)));
}
#define CPA16(dst, src) \
    asm volatile("cp.async.cg.shared.global [%0],[%1],16;" :: "r"(dst), "l"(src))
#define CPA_COMMIT() asm volatile("cp.async.commit_group;" ::: "memory")
#define CPA_WAIT0()  asm volatile("cp.async.wait_group 0;" ::: "memory")

// ============================================================================
// Attention + fused output projection. BM=128, 8 warps, 2 CTAs/SM.
// Loop tile: S(jt) | exp->P (f16x2 MUFU) | sync | cp.async QV(jt+1) | PV(jt)
//            | wait | sync
// ============================================================================
__global__ void __launch_bounds__(256, 2)
attn_mma(const __half* __restrict__ khg, const __half* __restrict__ vhg,
         const __half* __restrict__ qhg, const float* __restrict__ Wp,
         const float* __restrict__ bp, float* __restrict__ out) {
    extern __shared__ char smem[];
    const uint32_t sb = smem_u32(smem);
    const int tid = threadIdx.x, lane = tid & 31, wid = tid >> 5;
    const int q = lane & 3, lr = lane >> 2;
    const int b = blockIdx.y, row0 = blockIdx.x * BM;

    const __half* kh_b = khg + ((size_t)b * NN + row0) * DD;
    const __half* vh_b = vhg + (size_t)b * NN * DD;
    const __half* qh_b = qhg + (size_t)b * NN * DD;

    const int rg = wid >> 1, cg = wid & 1;   // S: 4x2 warp grid (32x32)
    const int r2 = wid >> 2, c2 = wid & 3;   // PV/proj: 2x4 warp grid (64x32)

    const int rA = (lane & 7) + (lane & 8), cA = (lane & 16) >> 1;   // A/P/V pattern
    const int rB = (lane & 7) + ((lane & 16) >> 1), cB = lane & 8;   // B (Q) pattern

    // ldmatrix bases
    uint32_t aK[2], bQ[2], aP[4], bV[2][2];
    #pragma unroll
    for (int mt = 0; mt < 2; ++mt)
        aK[mt] = sb + SM_K + 2u * ((32 * rg + 16 * mt + rA) * 136 + cA);
    #pragma unroll
    for (int bt = 0; bt < 2; ++bt)
        bQ[bt] = sb + SM_Q + 2u * ((32 * cg + 16 * bt + rB) * 136 + cB);
    #pragma unroll
    for (int mt = 0; mt < 4; ++mt)
        aP[mt] = sb + SM_P + 2u * ((64 * r2 + 16 * mt + rA) * 72 + cA);
    #pragma unroll
    for (int bf = 0; bf < 2; ++bf)
        #pragma unroll
        for (int bt = 0; bt < 2; ++bt)
            bV[bf][bt] = sb + SM_V + bf * TBUF +
                         2u * (rA * 136 + 32 * c2 + 16 * bt + cA);

    // stage K tile (resident during main loop)
    #pragma unroll
    for (int t = 0; t < 8; ++t) {
        int c = tid + (t << 8);
        int r = c >> 4, c16 = c & 15;
        *(uint4*)(smem + SM_K + (uint32_t)(r * 272 + c16 * 16)) =
            *(const uint4*)((const char*)(kh_b + (size_t)r * DD) + c16 * 16);
    }
    // prefetch tile 0 (Q, V buf0)
    #pragma unroll
    for (int t = 0; t < 4; ++t) {
        int c = tid + (t << 8);
        int m = c >> 4, c16 = c & 15;
        uint32_t dof = (uint32_t)(m * 272 + c16 * 16);
        CPA16(sb + SM_Q + dof, (const char*)(qh_b + (size_t)m * DD) + c16 * 16);
        CPA16(sb + SM_V + dof, (const char*)(vh_b + (size_t)m * DD) + c16 * 16);
    }
    CPA_COMMIT();
    CPA_WAIT0();
    __syncthreads();   // K + Q(0) + V(0) visible

    float sO[4][4][4];
    #pragma unroll
    for (int i = 0; i < 4; ++i)
        #pragma unroll
        for (int j = 0; j < 4; ++j) {
            sO[i][j][0] = 0.f; sO[i][j][1] = 0.f; sO[i][j][2] = 0.f; sO[i][j][3] = 0.f;
        }
    float lloc[4] = {0.f, 0.f, 0.f, 0.f};

    for (int jt = 0; jt < NT; ++jt) {
        const int vc = jt & 1;

        // ---- S(jt) = K @ Q^T : 32x32 warp tile, 8 k-steps ----
        float sC[2][4][4];
        #pragma unroll
        for (int i = 0; i < 2; ++i)
            #pragma unroll
            for (int j = 0; j < 4; ++j) {
                sC[i][j][0] = 0.f; sC[i][j][1] = 0.f; sC[i][j][2] = 0.f; sC[i][j][3] = 0.f;
            }
        #pragma unroll
        for (int ks = 0; ks < 8; ++ks) {
            uint32_t kf[2][4], qf[2][4];
            #pragma unroll
            for (int mt = 0; mt < 2; ++mt) ldsmx4(kf[mt], aK[mt] + ks * 32);
            #pragma unroll
            for (int bt = 0; bt < 2; ++bt) ldsmx4(qf[bt], bQ[bt] + ks * 32);
            #pragma unroll
            for (int mt = 0; mt < 2; ++mt)
                #pragma unroll
                for (int nt = 0; nt < 4; ++nt)
                    mma16816(sC[mt][nt], kf[mt],
                             qf[nt >> 1][2 * (nt & 1)], qf[nt >> 1][2 * (nt & 1) + 1]);
        }

        // ---- P(jt) = exp2(S) via f16x2 MUFU -> smem; fp16 partial row sums ----
        #pragma unroll
        for (int mt = 0; mt < 2; ++mt) {
            int rbase = 32 * rg + 16 * mt + lr;
            uint32_t hs0 = 0u, hs1 = 0u;   // half2 partial sums (rows rbase, rbase+8)
            #pragma unroll
            for (int nt = 0; nt < 4; ++nt) {
                int col = 32 * cg + 8 * nt + 2 * q;
                uint32_t p01 = ex2h2(packh2(sC[mt][nt][0], sC[mt][nt][1]));
                uint32_t p23 = ex2h2(packh2(sC[mt][nt][2], sC[mt][nt][3]));
                hs0 = hadd2(hs0, p01);
                hs1 = hadd2(hs1, p23);
                *(uint32_t*)(smem + SM_P + 2u * (rbase * 72 + col)) = p01;
                *(uint32_t*)(smem + SM_P + 2u * ((rbase + 8) * 72 + col)) = p23;
            }
            lloc[2 * mt]     += h2lo(hs0) + h2hi(hs0);
            lloc[2 * mt + 1] += h2lo(hs1) + h2hi(hs1);
        }
        __syncthreads();   // P visible; Q(jt) fully consumed

        // prefetch Q(jt+1), V(jt+1) — overlapped with PV below
        if (jt + 1 < NT) {
            const size_t m1 = (size_t)(jt + 1) * BN;
            #pragma unroll
            for (int t = 0; t < 4; ++t) {
                int c = tid + (t << 8);
                int m = c >> 4, c16 = c & 15;
                uint32_t dof = (uint32_t)(m * 272 + c16 * 16);
                CPA16(sb + SM_Q + dof,
                      (const char*)(qh_b + (m1 + m) * DD) + c16 * 16);
                CPA16(sb + SM_V + (vc ^ 1) * TBUF + dof,
                      (const char*)(vh_b + (m1 + m) * DD) + c16 * 16);
            }
            CPA_COMMIT();
        }

        // ---- PV(jt): O += P @ V : 64x32 warp tile, 4 k-steps ----
        #pragma unroll
        for (int ks = 0; ks < 4; ++ks) {
            uint32_t ph[4][4], vf[2][4];
            #pragma unroll
            for (int mt = 0; mt < 4; ++mt) ldsmx4(ph[mt], aP[mt] + ks * 32);
            #pragma unroll
            for (int bt = 0; bt < 2; ++bt) ldsmx4t(vf[bt], bV[vc][bt] + ks * 4352);
            #pragma unroll
            for (int mt = 0; mt < 4; ++mt)
                #pragma unroll
                for (int nt = 0; nt < 4; ++nt)
                    mma16816(sO[mt][nt], ph[mt],
                             vf[nt >> 1][2 * (nt & 1)], vf[nt >> 1][2 * (nt & 1) + 1]);
        }

        if (jt + 1 < NT) CPA_WAIT0();
        __syncthreads();   // PV(jt) done; QV(jt+1) arrived
    }

    // ---- l reduction: quad shfl + cross-colgroup via smem ----
    #pragma unroll
    for (int i = 0; i < 4; ++i) {
        lloc[i] += __shfl_xor_sync(0xffffffffu, lloc[i], 1);
        lloc[i] += __shfl_xor_sync(0xffffffffu, lloc[i], 2);
    }
    float* lsum = (float*)(smem + SM_LS);
    if (q == 0) {
        #pragma unroll
        for (int i = 0; i < 4; ++i) {
            int row = 32 * rg + 16 * (i >> 1) + 8 * (i & 1) + lr;
            lsum[cg * 128 + row] = lloc[i];
        }
    }
    __syncthreads();

    // ---- epilogue part 1: O/l -> fp16 into SM_K (pitch 136); Wp -> SM_Q ----
    #pragma unroll
    for (int mt = 0; mt < 4; ++mt) {
        int ra = 64 * r2 + 16 * mt + lr;
        float inva = 1.0f / (lsum[ra] + lsum[128 + ra]);
        float invb = 1.0f / (lsum[ra + 8] + lsum[128 + ra + 8]);
        #pragma unroll
        for (int nt = 0; nt < 4; ++nt) {
            int col = 32 * c2 + 8 * nt + 2 * q;
            *(uint32_t*)(smem + SM_K + 2u * (ra * 136 + col)) =
                packh2(sO[mt][nt][0] * inva, sO[mt][nt][1] * inva);
            *(uint32_t*)(smem + SM_K + 2u * ((ra + 8) * 136 + col)) =
                packh2(sO[mt][nt][2] * invb, sO[mt][nt][3] * invb);
        }
    }
    #pragma unroll
    for (int it = 0; it < 16; ++it) {   // Wp fp32 -> fp16 (pitch 136), [k][n]
        int f = tid + (it << 8);
        int k = f >> 5, c4 = f & 31;
        float4 v = *(const float4*)(Wp + (size_t)k * 128 + (c4 << 2));
        uint2 h; h.x = packh2(v.x, v.y); h.y = packh2(v.z, v.w);
        *(uint2*)(smem + SM_Q + (uint32_t)(k * 272 + (c4 << 3))) = h;
    }
    __syncthreads();

    // ---- epilogue part 2: out = Onorm @ Wp + bp (128x128 HMMA) ----
    {
        uint32_t aB[4], bB[2];
        #pragma unroll
        for (int mt = 0; mt < 4; ++mt)
            aB[mt] = sb + SM_K + 2u * ((64 * r2 + 16 * mt + rA) * 136 + cA);
        #pragma unroll
        for (int bt = 0; bt < 2; ++bt)
            bB[bt] = sb + SM_Q + 2u * (rA * 136 + 32 * c2 + 16 * bt + cA);

        float acc[4][4][4];
        #pragma unroll
        for (int i = 0; i < 4; ++i)
            #pragma unroll
            for (int j = 0; j < 4; ++j) {
                acc[i][j][0] = 0.f; acc[i][j][1] = 0.f;
                acc[i][j][2] = 0.f; acc[i][j][3] = 0.f;
            }
        #pragma unroll
        for (int ks = 0; ks < 8; ++ks) {
            uint32_t a[4][4], bf[2][4];
            #pragma unroll
            for (int mt = 0; mt < 4; ++mt) ldsmx4(a[mt], aB[mt] + ks * 32);
            #pragma unroll
            for (int bt = 0; bt < 2; ++bt) ldsmx4t(bf[bt], bB[bt] + ks * 4352);
            #pragma unroll
            for (int mt = 0; mt < 4; ++mt)
                #pragma unroll
                for (int nt = 0; nt < 4; ++nt)
                    mma16816(acc[mt][nt], a[mt],
                             bf[nt >> 1][2 * (nt & 1)], bf[nt >> 1][2 * (nt & 1) + 1]);
        }

        float* ob = out + ((size_t)b * NN + row0) * DD;
        #pragma unroll
        for (int mt = 0; mt < 4; ++mt) {
            int ra = 64 * r2 + 16 * mt + lr;
            #pragma unroll
            for (int nt = 0; nt < 4; ++nt) {
                int col = 32 * c2 + 8 * nt + 2 * q;
                float b0 = bp[col], b1 = bp[col + 1];
                *(float2*)(ob + (size_t)ra * DD + col) =
                    make_float2(acc[mt][nt][0] + b0, acc[mt][nt][1] + b1);
                *(float2*)(ob + (size_t)(ra + 8) * DD + col) =
                    make_float2(acc[mt][nt][2] + b0, acc[mt][nt][3] + b1);
            }
        }
    }
}

// ============================================================================
// fp16 tensor-core kv projection (128x128 CTA tile) + fused Q conversion
// grid (3, M/128): x in {0,1} -> kv cols; x==2 -> Q fp32->fp16 (scaled)
// ============================================================================
__device__ __forceinline__ uint32_t pack_us2(__half a, __half b) {
    return (uint32_t)__half_as_ushort(a) | ((uint32_t)__half_as_ushort(b) << 16);
}

__global__ void __launch_bounds__(256, 2)
gemm16_kv(const float* __restrict__ A, const float* __restrict__ W,
          const float* __restrict__ bias, const float* __restrict__ qg,
          __half* __restrict__ kh, __half* __restrict__ vh,
          __half* __restrict__ qh) {
    if (blockIdx.x == 2) {   // fused qconv: 128 rows of Q per y-block
        const size_t base = (size_t)blockIdx.y * (128 * 128 / 4);
        const float4* src = (const float4*)qg + base;
        __half2* dst = (__half2*)qh + base * 2;
        #pragma unroll
        for (int t = 0; t < 16; ++t) {
            int f = threadIdx.x + (t << 8);
            float4 v = src[f];
            dst[2 * f]     = __floats2half2_rn(v.x * QS, v.y * QS);
            dst[2 * f + 1] = __floats2half2_rn(v.z * QS, v.w * QS);
        }
        return;
    }

    extern __shared__ char smg[];
    const uint32_t sb = smem_u32(smg);
    const int tid = threadIdx.x, lane = tid & 31, wid = tid >> 5;
    const int q = lane & 3, lr = lane >> 2;
    const int rw = wid >> 2, cw = wid & 3;
    const int row0 = blockIdx.y * 128, col0 = blockIdx.x * 128;

    #pragma unroll
    for (int it = 0; it < 16; ++it) {
        int f = tid + (it << 8);
        int r = f >> 5, c4 = f & 31;
        float4 v = *(const float4*)(A + (size_t)(row0 + r) * 128 + (c4 << 2));
        uint2 h; h.x = packh2(v.x, v.y); h.y = packh2(v.z, v.w);
        *(uint2*)(smg + (uint32_t)(r * 272 + (c4 << 3))) = h;
    }
    #pragma unroll
    for (int it = 0; it < 16; ++it) {
        int f = tid + (it << 8);
        int k = f >> 5, c4 = f & 31;
        float4 v = *(const float4*)(W + (size_t)k * 256 + col0 + (c4 << 2));
        uint2 h; h.x = packh2(v.x, v.y); h.y = packh2(v.z, v.w);
        *(uint2*)(smg + 34816 + (uint32_t)(k * 272 + (c4 << 3))) = h;
    }
    __syncthreads();

    const int rA = (lane & 7) + (lane & 8), cA = (lane & 16) >> 1;
    uint32_t aBase[4], bBase[2];
    #pragma unroll
    for (int mt = 0; mt < 4; ++mt)
        aBase[mt] = sb + 2u * ((64 * rw + 16 * mt + rA) * 136 + cA);
    #pragma unroll
    for (int bt = 0; bt < 2; ++bt)
        bBase[bt] = sb + 34816 + 2u * (rA * 136 + 32 * cw + 16 * bt + cA);

    float acc[4][4][4];
    #pragma unroll
    for (int i = 0; i < 4; ++i)
        #pragma unroll
        for (int j = 0; j < 4; ++j) {
            acc[i][j][0] = 0.f; acc[i][j][1] = 0.f; acc[i][j][2] = 0.f; acc[i][j][3] = 0.f;
        }
    #pragma unroll
    for (int ks = 0; ks < 8; ++ks) {
        uint32_t a[4][4], bf[2][4];
        #pragma unroll
        for (int mt = 0; mt < 4; ++mt) ldsmx4(a[mt], aBase[mt] + ks * 32);
        #pragma unroll
        for (int bt = 0; bt < 2; ++bt) ldsmx4t(bf[bt], bBase[bt] + ks * 4352);
        #pragma unroll
        for (int mt = 0; mt < 4; ++mt)
            #pragma unroll
            for (int nt = 0; nt < 4; ++nt)
                mma16816(acc[mt][nt], a[mt],
                         bf[nt >> 1][2 * (nt & 1)], bf[nt >> 1][2 * (nt & 1) + 1]);
    }

    __half* dh = (col0 == 0) ? kh : vh;
    #pragma unroll
    for (int mt = 0; mt < 4; ++mt) {
        int r = row0 + 64 * rw + 16 * mt + lr;
        #pragma unroll
        for (int nt = 0; nt < 4; ++nt) {
            int col = 32 * cw + 8 * nt + 2 * q;
            float b0 = bias[col0 + col], b1 = bias[col0 + col + 1];
            *(uint32_t*)(dh + (size_t)r * 128 + col) = pack_us2(
                __float2half_rn(acc[mt][nt][0] + b0), __float2half_rn(acc[mt][nt][1] + b1));
            *(uint32_t*)(dh + (size_t)(r + 8) * 128 + col) = pack_us2(
                __float2half_rn(acc[mt][nt][2] + b0), __float2half_rn(acc[mt][nt][3] + b1));
        }
    }
}

// ============================================================================
extern "C" void kernel_launch(void* const* d_in, const int* in_sizes, int n_in,
                              void* d_out, int out_size) {
    const float* x   = (const float*)d_in[0];
    const float* qg  = (const float*)d_in[1];
    const float* Wkv = (const float*)d_in[2];
    const float* bkv = (const float*)d_in[3];
    const float* Wp  = (const float*)d_in[4];
    const float* bp  = (const float*)d_in[5];
    float* out = (float*)d_out;

    __half *khp, *vhp, *qhp;
    cudaGetSymbolAddress((void**)&khp, g_kh);
    cudaGetSymbolAddress((void**)&vhp, g_vh);
    cudaGetSymbolAddress((void**)&qhp, g_qh);

    const int M = BB * NN;
    const int gsm = 2 * 128 * 272;  // 69632 B

    cudaFuncSetAttribute(gemm16_kv,
                         cudaFuncAttributeMaxDynamicSharedMemorySize, gsm);
    cudaFuncSetAttribute(attn_mma,
                         cudaFuncAttributeMaxDynamicSharedMemorySize, SM_TOT);

    gemm16_kv<<<dim3(3, M / 128), 256, gsm>>>(x, Wkv, bkv, qg, khp, vhp, qhp);
    attn_mma<<<dim3(NN / BM, BB), 256, SM_TOT>>>(khp, vhp, qhp, Wp, bp, out);
}